// round 5
// baseline (speedup 1.0000x reference)
#include <cuda_runtime.h>
#include <cuda_fp16.h>
#include <cuda_bf16.h>
#include <cstdint>

// ---------------- problem constants ----------------
#define GN 100000          // nodes
#define GD 256             // d_in = d_out
#define GK 512             // 2*d_in
#define MAXDEG 16

// ---------------- scratch (device globals; no allocs allowed) ----------------
__device__ __align__(256) __half g_xh[(GN + 1) * GD];   // x in fp16, + zero row at index GN
__device__ __align__(256) __half g_aggh[GN * GD];       // neighbor mean, fp16
__device__ __align__(256) __half g_wh[GK * GD];         // W in fp16, [n][k] row-major (k contiguous)
__device__ int g_is64;                                  // edge_index dtype flag

// ---------------- small helpers ----------------
__device__ __forceinline__ uint32_t smem_u32(const void* p) {
    uint32_t a;
    asm("{ .reg .u64 t; cvta.to.shared.u64 t, %1; cvt.u32.u64 %0, t; }" : "=r"(a) : "l"(p));
    return a;
}

__device__ __forceinline__ void cp_async16(uint32_t dst, const void* src, int pred) {
    int sz = pred ? 16 : 0;
    asm volatile("cp.async.cg.shared.global [%0], [%1], 16, %2;"
                 :: "r"(dst), "l"(src), "r"(sz) : "memory");
}
__device__ __forceinline__ void cp_async_commit() {
    asm volatile("cp.async.commit_group;" ::: "memory");
}
__device__ __forceinline__ void cp_async_wait0() {
    asm volatile("cp.async.wait_group 0;" ::: "memory");
}

__device__ __forceinline__ void ldsm_x4(uint32_t& r0, uint32_t& r1, uint32_t& r2, uint32_t& r3,
                                        uint32_t addr) {
    asm volatile("ldmatrix.sync.aligned.m8n8.x4.shared.b16 {%0,%1,%2,%3}, [%4];"
                 : "=r"(r0), "=r"(r1), "=r"(r2), "=r"(r3) : "r"(addr));
}

__device__ __forceinline__ void mma16816(float& c0, float& c1, float& c2, float& c3,
                                         uint32_t a0, uint32_t a1, uint32_t a2, uint32_t a3,
                                         uint32_t b0, uint32_t b1) {
    asm volatile(
        "mma.sync.aligned.m16n8k16.row.col.f32.f16.f16.f32 "
        "{%0,%1,%2,%3}, {%4,%5,%6,%7}, {%8,%9}, {%0,%1,%2,%3};"
        : "+f"(c0), "+f"(c1), "+f"(c2), "+f"(c3)
        : "r"(a0), "r"(a1), "r"(a2), "r"(a3), "r"(b0), "r"(b1));
}

// ---------------- kernel 1: x -> fp16 (+ zero pad row) ----------------
__global__ void cvt_x_kernel(const float* __restrict__ x) {
    size_t i = ((size_t)blockIdx.x * blockDim.x + threadIdx.x) * 8;
    const size_t total = (size_t)(GN + 1) * GD;
    if (i >= total) return;
    uint4 o;
    if (i < (size_t)GN * GD) {
        float4 a = *(const float4*)(x + i);
        float4 b = *(const float4*)(x + i + 4);
        __half2 h0 = __floats2half2_rn(a.x, a.y);
        __half2 h1 = __floats2half2_rn(a.z, a.w);
        __half2 h2 = __floats2half2_rn(b.x, b.y);
        __half2 h3 = __floats2half2_rn(b.z, b.w);
        o.x = *reinterpret_cast<unsigned*>(&h0);
        o.y = *reinterpret_cast<unsigned*>(&h1);
        o.z = *reinterpret_cast<unsigned*>(&h2);
        o.w = *reinterpret_cast<unsigned*>(&h3);
    } else {
        o = make_uint4(0, 0, 0, 0);
    }
    *(uint4*)(g_xh + i) = o;
}

// ---------------- kernel 1w: W -> fp16 ----------------
__global__ void cvt_w_kernel(const float* __restrict__ W) {
    size_t i = ((size_t)blockIdx.x * blockDim.x + threadIdx.x) * 8;
    if (i >= (size_t)GD * GK) return;
    float4 a = *(const float4*)(W + i);
    float4 b = *(const float4*)(W + i + 4);
    __half2 h0 = __floats2half2_rn(a.x, a.y);
    __half2 h1 = __floats2half2_rn(a.z, a.w);
    __half2 h2 = __floats2half2_rn(b.x, b.y);
    __half2 h3 = __floats2half2_rn(b.z, b.w);
    uint4 o;
    o.x = *reinterpret_cast<unsigned*>(&h0);
    o.y = *reinterpret_cast<unsigned*>(&h1);
    o.z = *reinterpret_cast<unsigned*>(&h2);
    o.w = *reinterpret_cast<unsigned*>(&h3);
    *(uint4*)(g_wh + i) = o;
}

// ---------------- kernel 1b: detect edge dtype (int32 vs int64) ----------------
__global__ void detect_kernel(const int* __restrict__ e) {
    int v = e[2 * threadIdx.x + 1];           // odd 32-bit words of first rows
    int bad = (v != 0 && v != -1) ? 1 : 0;    // int64 => these are all 0 / -1
    int any = __syncthreads_or(bad);
    if (threadIdx.x == 0) g_is64 = any ? 0 : 1;
}

// ---------------- kernel 2: mean aggregation (one warp per node) ----------------
// 8 gathers in flight per batch (MLP=8), depth-3 HADD2 tree, fp32 across batches.
__global__ void agg_kernel(const int* __restrict__ edges) {
    int node = (int)((blockIdx.x * blockDim.x + threadIdx.x) >> 5);
    int lane = threadIdx.x & 31;
    if (node >= GN) return;
    int is64 = g_is64;
    int e = -1;
    if (lane < MAXDEG) {
        if (is64) {
            long long t = ((const long long*)edges)[(size_t)node * MAXDEG + lane];
            e = (int)t;
        } else {
            e = edges[node * MAXDEG + lane];
        }
    }
    unsigned bal = __ballot_sync(0xffffffffu, e >= 0);
    float inv = 1.0f / (float)__popc(bal & 0xffffu);

    float acc[8];
#pragma unroll
    for (int q = 0; q < 8; q++) acc[q] = 0.0f;

#pragma unroll
    for (int h = 0; h < 2; h++) {             // two batches of 8 neighbors
        uint4 v[8];
#pragma unroll
        for (int d = 0; d < 8; d++) {
            int ej = __shfl_sync(0xffffffffu, e, h * 8 + d);
            unsigned row = (ej >= 0) ? (unsigned)ej : (unsigned)GN;   // pad -> zero row
            v[d] = *(const uint4*)(g_xh + (size_t)row * GD + lane * 8);
        }
        const __half2* p0 = (const __half2*)&v[0];
        const __half2* p1 = (const __half2*)&v[1];
        const __half2* p2 = (const __half2*)&v[2];
        const __half2* p3 = (const __half2*)&v[3];
        const __half2* p4 = (const __half2*)&v[4];
        const __half2* p5 = (const __half2*)&v[5];
        const __half2* p6 = (const __half2*)&v[6];
        const __half2* p7 = (const __half2*)&v[7];
#pragma unroll
        for (int j = 0; j < 4; j++) {
            __half2 s01 = __hadd2(p0[j], p1[j]);
            __half2 s23 = __hadd2(p2[j], p3[j]);
            __half2 s45 = __hadd2(p4[j], p5[j]);
            __half2 s67 = __hadd2(p6[j], p7[j]);
            __half2 sA = __hadd2(s01, s23);
            __half2 sB = __hadd2(s45, s67);
            __half2 s = __hadd2(sA, sB);
            float2 f = __half22float2(s);
            acc[j * 2] += f.x;
            acc[j * 2 + 1] += f.y;
        }
    }
    __half2 r0 = __floats2half2_rn(acc[0] * inv, acc[1] * inv);
    __half2 r1 = __floats2half2_rn(acc[2] * inv, acc[3] * inv);
    __half2 r2 = __floats2half2_rn(acc[4] * inv, acc[5] * inv);
    __half2 r3 = __floats2half2_rn(acc[6] * inv, acc[7] * inv);
    uint4 o;
    o.x = *reinterpret_cast<unsigned*>(&r0);
    o.y = *reinterpret_cast<unsigned*>(&r1);
    o.z = *reinterpret_cast<unsigned*>(&r2);
    o.w = *reinterpret_cast<unsigned*>(&r3);
    *(uint4*)(g_aggh + (size_t)node * GD + lane * 8) = o;
}

// ---------------- kernel 3: mma.sync GEMM  out[M,256] = h[M,512] @ W^T + b ------------
// h = [x | agg] (fp16), W fp16 [n][k]. CTA: 512 thr (16 warps, 4/SMSP),
// tile 128(M) x 256(N), K chunks of 64, double-buffered cp.async.
// Warp grid 2(M) x 8(N), warp tile 64x32 -> 64 fp32 acc/thread.

#define TILE_M 128
#define KC 64
#define NCH 8

// SMEM: A[2] 16KB @ 0; B[2] 32KB @ 32768. 16B-seg XOR swizzle. Total 96KB.
#define SA(buf) ((buf) * 16384)
#define SB(buf) (32768 + (buf) * 32768)
#define SMEM_DYN 98304

__global__ void __launch_bounds__(512, 1)
gemm_kernel(const float* __restrict__ bias, float* __restrict__ out) {
    extern __shared__ char smem_raw[];
    uint32_t sb = smem_u32(smem_raw);
    const int tid = threadIdx.x;
    const int wid = tid >> 5, lane = tid & 31;
    const int warp_m = wid & 1;          // 0..1 -> 64 rows
    const int warp_n = wid >> 1;         // 0..7 -> 32 cols
    const int m0 = blockIdx.x * TILE_M;

    // ---- cp.async issue: A = 1024 16B segs, B = 2048 16B segs, 512 threads ----
    auto issue_chunk = [&](int c, int buf) {
        const __half* asrc = (c < 4) ? g_xh : g_aggh;
        int kc0 = (c & 3) * KC;
#pragma unroll
        for (int i = 0; i < 2; i++) {
            int s = tid + i * 512;
            int row = s >> 3, seg = s & 7;
            int m = m0 + row;
            uint32_t dst = sb + SA(buf) + row * 128 + ((seg ^ (row & 7)) << 4);
            cp_async16(dst, asrc + (size_t)m * GD + kc0 + seg * 8, m < GN);
        }
#pragma unroll
        for (int i = 0; i < 4; i++) {
            int s = tid + i * 512;
            int n = s >> 3, seg = s & 7;
            uint32_t dst = sb + SB(buf) + n * 128 + ((seg ^ (n & 7)) << 4);
            cp_async16(dst, g_wh + (size_t)n * GK + c * KC + seg * 8, 1);
        }
        cp_async_commit();
    };

    float acc[4][4][4];
#pragma unroll
    for (int mt = 0; mt < 4; mt++)
#pragma unroll
        for (int nt = 0; nt < 4; nt++)
#pragma unroll
            for (int q = 0; q < 4; q++) acc[mt][nt][q] = 0.0f;

    issue_chunk(0, 0);

    const int lrow = lane & 15;          // row within 16-row tile
    const int lcg = lane >> 4;           // 16B column group (0/1)

#pragma unroll 1
    for (int c = 0; c < NCH; c++) {
        cp_async_wait0();
        __syncthreads();
        if (c + 1 < NCH) issue_chunk(c + 1, (c + 1) & 1);

        uint32_t abase = sb + SA(c & 1);
        uint32_t bbase = sb + SB(c & 1);
#pragma unroll
        for (int ks = 0; ks < 4; ks++) {
            uint32_t a0[4], a1[4], a2[4], a3[4];
            uint32_t b0[2], b1[2], b2[2], b3[2];
#pragma unroll
            for (int mt = 0; mt < 4; mt++) {
                int row = warp_m * 64 + mt * 16 + lrow;
                uint32_t addr = abase + row * 128 + (((ks * 2 + lcg) ^ (row & 7)) << 4);
                ldsm_x4(a0[mt], a1[mt], a2[mt], a3[mt], addr);
            }
#pragma unroll
            for (int np = 0; np < 2; np++) {       // 2 n-tile pairs (16 n-rows each)
                int row = warp_n * 32 + np * 16 + lrow;
                uint32_t addr = bbase + row * 128 + (((ks * 2 + lcg) ^ (row & 7)) << 4);
                ldsm_x4(b0[np], b1[np], b2[np], b3[np], addr);
            }
#pragma unroll
            for (int mt = 0; mt < 4; mt++) {
#pragma unroll
                for (int np = 0; np < 2; np++) {
                    mma16816(acc[mt][np * 2][0], acc[mt][np * 2][1],
                             acc[mt][np * 2][2], acc[mt][np * 2][3],
                             a0[mt], a1[mt], a2[mt], a3[mt], b0[np], b2[np]);
                    mma16816(acc[mt][np * 2 + 1][0], acc[mt][np * 2 + 1][1],
                             acc[mt][np * 2 + 1][2], acc[mt][np * 2 + 1][3],
                             a0[mt], a1[mt], a2[mt], a3[mt], b1[np], b3[np]);
                }
            }
        }
        __syncthreads();
    }

    // ---- epilogue: bias + store ----
    const int qm = lane >> 2;            // 0..7 row within 8
    const int qn = (lane & 3) * 2;       // col pair
    float2 bb[4];
#pragma unroll
    for (int nt = 0; nt < 4; nt++) {
        int ncol = warp_n * 32 + nt * 8 + qn;
        bb[nt] = *(const float2*)(bias + ncol);
    }
#pragma unroll
    for (int mt = 0; mt < 4; mt++) {
        int r0 = m0 + warp_m * 64 + mt * 16 + qm;
        int r1 = r0 + 8;
#pragma unroll
        for (int nt = 0; nt < 4; nt++) {
            int ncol = warp_n * 32 + nt * 8 + qn;
            if (r0 < GN) {
                float2 v = make_float2(acc[mt][nt][0] + bb[nt].x, acc[mt][nt][1] + bb[nt].y);
                *(float2*)(out + (size_t)r0 * GD + ncol) = v;
            }
            if (r1 < GN) {
                float2 v = make_float2(acc[mt][nt][2] + bb[nt].x, acc[mt][nt][3] + bb[nt].y);
                *(float2*)(out + (size_t)r1 * GD + ncol) = v;
            }
        }
    }
}

// ---------------- launch ----------------
extern "C" void kernel_launch(void* const* d_in, const int* in_sizes, int n_in,
                              void* d_out, int out_size) {
    const float* x  = (const float*)d_in[0];
    const int*   ei = (const int*)d_in[1];
    const float* W  = (const float*)d_in[2];
    const float* b  = (const float*)d_in[3];
    float* out = (float*)d_out;
    (void)in_sizes; (void)n_in; (void)out_size;

    static int attr_done = 0;
    if (!attr_done) {
        cudaFuncSetAttribute(gemm_kernel, cudaFuncAttributeMaxDynamicSharedMemorySize, SMEM_DYN);
        attr_done = 1;
    }

    // 1) x -> fp16 (+ zero pad row), W -> fp16
    int cvt_threads = ((GN + 1) * GD) / 8;
    cvt_x_kernel<<<(cvt_threads + 255) / 256, 256>>>(x);
    cvt_w_kernel<<<(GD * GK / 8 + 255) / 256, 256>>>(W);
    // 1b) edge dtype detection (int32 vs silently-int64)
    detect_kernel<<<1, 256>>>(ei);
    // 2) gather + mean (one warp per node, MLP=8)
    agg_kernel<<<GN / 8, 256>>>(ei);
    // 3) mma.sync fp16 GEMM + bias (512 threads, 16 warps)
    gemm_kernel<<<(GN + TILE_M - 1) / TILE_M, 512, SMEM_DYN>>>(b, out);
}

// round 6
// speedup vs baseline: 1.0128x; 1.0128x over previous
#include <cuda_runtime.h>
#include <cuda_fp16.h>
#include <cuda_bf16.h>
#include <cstdint>

// ---------------- problem constants ----------------
#define GN 100000          // nodes
#define GD 256             // d_in = d_out
#define GK 512             // 2*d_in
#define MAXDEG 16

#define TILE_M 128
#define TOTAL_CTAS ((GN + TILE_M - 1) / TILE_M)   // 782
#define STRIP_CTAS 148                            // one full wave at 1 CTA/SM
#define NSTRIP 6                                  // 5*148 + 42

// ---------------- scratch (device globals; no allocs allowed) ----------------
__device__ __align__(256) __half g_xh[(GN + 1) * GD];   // x in fp16, + zero row at index GN
__device__ __align__(256) __half g_aggh[GN * GD];       // neighbor mean, fp16
__device__ __align__(256) __half g_wh[GK * GD];         // W in fp16, [n][k] row-major
__device__ int g_is64;                                  // edge_index dtype flag

// ---------------- small helpers ----------------
__device__ __forceinline__ uint32_t smem_u32(const void* p) {
    uint32_t a;
    asm("{ .reg .u64 t; cvta.to.shared.u64 t, %1; cvt.u32.u64 %0, t; }" : "=r"(a) : "l"(p));
    return a;
}

__device__ __forceinline__ void cp_async16(uint32_t dst, const void* src, int pred) {
    int sz = pred ? 16 : 0;
    asm volatile("cp.async.cg.shared.global [%0], [%1], 16, %2;"
                 :: "r"(dst), "l"(src), "r"(sz) : "memory");
}
__device__ __forceinline__ void cp_async_commit() {
    asm volatile("cp.async.commit_group;" ::: "memory");
}
__device__ __forceinline__ void cp_async_wait0() {
    asm volatile("cp.async.wait_group 0;" ::: "memory");
}

__device__ __forceinline__ void ldsm_x4(uint32_t& r0, uint32_t& r1, uint32_t& r2, uint32_t& r3,
                                        uint32_t addr) {
    asm volatile("ldmatrix.sync.aligned.m8n8.x4.shared.b16 {%0,%1,%2,%3}, [%4];"
                 : "=r"(r0), "=r"(r1), "=r"(r2), "=r"(r3) : "r"(addr));
}

__device__ __forceinline__ void mma16816(float& c0, float& c1, float& c2, float& c3,
                                         uint32_t a0, uint32_t a1, uint32_t a2, uint32_t a3,
                                         uint32_t b0, uint32_t b1) {
    asm volatile(
        "mma.sync.aligned.m16n8k16.row.col.f32.f16.f16.f32 "
        "{%0,%1,%2,%3}, {%4,%5,%6,%7}, {%8,%9}, {%0,%1,%2,%3};"
        : "+f"(c0), "+f"(c1), "+f"(c2), "+f"(c3)
        : "r"(a0), "r"(a1), "r"(a2), "r"(a3), "r"(b0), "r"(b1));
}

// ---------------- kernel 1: x -> fp16 (+ zero pad row) ----------------
__global__ void cvt_x_kernel(const float* __restrict__ x) {
    size_t i = ((size_t)blockIdx.x * blockDim.x + threadIdx.x) * 8;
    const size_t total = (size_t)(GN + 1) * GD;
    if (i >= total) return;
    uint4 o;
    if (i < (size_t)GN * GD) {
        float4 a = *(const float4*)(x + i);
        float4 b = *(const float4*)(x + i + 4);
        __half2 h0 = __floats2half2_rn(a.x, a.y);
        __half2 h1 = __floats2half2_rn(a.z, a.w);
        __half2 h2 = __floats2half2_rn(b.x, b.y);
        __half2 h3 = __floats2half2_rn(b.z, b.w);
        o.x = *reinterpret_cast<unsigned*>(&h0);
        o.y = *reinterpret_cast<unsigned*>(&h1);
        o.z = *reinterpret_cast<unsigned*>(&h2);
        o.w = *reinterpret_cast<unsigned*>(&h3);
    } else {
        o = make_uint4(0, 0, 0, 0);
    }
    *(uint4*)(g_xh + i) = o;
}

// ---------------- kernel 1w: W -> fp16 ----------------
__global__ void cvt_w_kernel(const float* __restrict__ W) {
    size_t i = ((size_t)blockIdx.x * blockDim.x + threadIdx.x) * 8;
    if (i >= (size_t)GD * GK) return;
    float4 a = *(const float4*)(W + i);
    float4 b = *(const float4*)(W + i + 4);
    __half2 h0 = __floats2half2_rn(a.x, a.y);
    __half2 h1 = __floats2half2_rn(a.z, a.w);
    __half2 h2 = __floats2half2_rn(b.x, b.y);
    __half2 h3 = __floats2half2_rn(b.z, b.w);
    uint4 o;
    o.x = *reinterpret_cast<unsigned*>(&h0);
    o.y = *reinterpret_cast<unsigned*>(&h1);
    o.z = *reinterpret_cast<unsigned*>(&h2);
    o.w = *reinterpret_cast<unsigned*>(&h3);
    *(uint4*)(g_wh + i) = o;
}

// ---------------- kernel 1b: detect edge dtype (int32 vs int64) ----------------
__global__ void detect_kernel(const int* __restrict__ e) {
    int v = e[2 * threadIdx.x + 1];           // odd 32-bit words of first rows
    int bad = (v != 0 && v != -1) ? 1 : 0;    // int64 => these are all 0 / -1
    int any = __syncthreads_or(bad);
    if (threadIdx.x == 0) g_is64 = any ? 0 : 1;
}

// ---------------- kernel 2: mean aggregation (one warp per node), strip version ------
// quad-at-a-time gather, depth-2 HADD2 tree + fp32 across quads (R4 config: 34 regs).
__global__ void agg_kernel(const int* __restrict__ edges, int nbase, int nend) {
    int node = nbase + (int)((blockIdx.x * blockDim.x + threadIdx.x) >> 5);
    int lane = threadIdx.x & 31;
    if (node >= nend) return;
    int is64 = g_is64;
    int e = -1;
    if (lane < MAXDEG) {
        if (is64) {
            long long t = ((const long long*)edges)[(size_t)node * MAXDEG + lane];
            e = (int)t;
        } else {
            e = edges[node * MAXDEG + lane];
        }
    }
    unsigned bal = __ballot_sync(0xffffffffu, e >= 0);
    float inv = 1.0f / (float)__popc(bal & 0xffffu);

    float acc[8];
#pragma unroll
    for (int q = 0; q < 8; q++) acc[q] = 0.0f;

#pragma unroll
    for (int q4 = 0; q4 < 4; q4++) {          // 4 quads of neighbors
        uint4 v[4];
#pragma unroll
        for (int d = 0; d < 4; d++) {
            int ej = __shfl_sync(0xffffffffu, e, q4 * 4 + d);
            unsigned row = (ej >= 0) ? (unsigned)ej : (unsigned)GN;   // pad -> zero row
            v[d] = *(const uint4*)(g_xh + (size_t)row * GD + lane * 8);
        }
        const __half2* p0 = (const __half2*)&v[0];
        const __half2* p1 = (const __half2*)&v[1];
        const __half2* p2 = (const __half2*)&v[2];
        const __half2* p3 = (const __half2*)&v[3];
#pragma unroll
        for (int j = 0; j < 4; j++) {
            __half2 s01 = __hadd2(p0[j], p1[j]);
            __half2 s23 = __hadd2(p2[j], p3[j]);
            __half2 s = __hadd2(s01, s23);
            float2 f = __half22float2(s);
            acc[j * 2] += f.x;
            acc[j * 2 + 1] += f.y;
        }
    }
    __half2 r0 = __floats2half2_rn(acc[0] * inv, acc[1] * inv);
    __half2 r1 = __floats2half2_rn(acc[2] * inv, acc[3] * inv);
    __half2 r2 = __floats2half2_rn(acc[4] * inv, acc[5] * inv);
    __half2 r3 = __floats2half2_rn(acc[6] * inv, acc[7] * inv);
    uint4 o;
    o.x = *reinterpret_cast<unsigned*>(&r0);
    o.y = *reinterpret_cast<unsigned*>(&r1);
    o.z = *reinterpret_cast<unsigned*>(&r2);
    o.w = *reinterpret_cast<unsigned*>(&r3);
    *(uint4*)(g_aggh + (size_t)node * GD + lane * 8) = o;
}

// ---------------- kernel 3: mma.sync GEMM strip  out[M,256] = h[M,512] @ W^T + b -----
// CTA: 256 thr (8 warps), tile 128(M) x 256(N), K chunks of 64, double-buffered.
// Warp grid 2(M) x 4(N), warp tile 64x64 (R4 config).

#define KC 64
#define NCH 8

// SMEM: A[2] @ 0, 16KB each ; B[2] @ 32768, 32KB each. 16B-seg XOR swizzle.
#define SA(buf) ((buf) * 16384)
#define SB(buf) (32768 + (buf) * 32768)
#define SMEM_DYN 98304

__global__ void __launch_bounds__(256, 1)
gemm_kernel(const float* __restrict__ bias, float* __restrict__ out, int m_base) {
    extern __shared__ char smem_raw[];
    uint32_t sb = smem_u32(smem_raw);
    const int tid = threadIdx.x;
    const int wid = tid >> 5, lane = tid & 31;
    const int warp_m = wid & 1;          // 0..1  -> 64 rows
    const int warp_n = wid >> 1;         // 0..3  -> 64 cols
    const int m0 = m_base + blockIdx.x * TILE_M;

    auto issue_chunk = [&](int c, int buf) {
        const __half* asrc = (c < 4) ? g_xh : g_aggh;
        int kc0 = (c & 3) * KC;
#pragma unroll
        for (int i = 0; i < 4; i++) {
            int s = tid + i * 256;
            int row = s >> 3, seg = s & 7;
            int m = m0 + row;
            uint32_t dst = sb + SA(buf) + row * 128 + ((seg ^ (row & 7)) << 4);
            cp_async16(dst, asrc + (size_t)m * GD + kc0 + seg * 8, m < GN);
        }
#pragma unroll
        for (int i = 0; i < 8; i++) {
            int s = tid + i * 256;
            int n = s >> 3, seg = s & 7;
            uint32_t dst = sb + SB(buf) + n * 128 + ((seg ^ (n & 7)) << 4);
            cp_async16(dst, g_wh + (size_t)n * GK + c * KC + seg * 8, 1);
        }
        cp_async_commit();
    };

    float acc[4][8][4];
#pragma unroll
    for (int mt = 0; mt < 4; mt++)
#pragma unroll
        for (int nt = 0; nt < 8; nt++)
#pragma unroll
            for (int q = 0; q < 4; q++) acc[mt][nt][q] = 0.0f;

    issue_chunk(0, 0);

    const int lrow = lane & 15;          // row within 16-row tile
    const int lcg = lane >> 4;           // 16B column group (0/1)

#pragma unroll 1
    for (int c = 0; c < NCH; c++) {
        cp_async_wait0();
        __syncthreads();
        if (c + 1 < NCH) issue_chunk(c + 1, (c + 1) & 1);

        uint32_t abase = sb + SA(c & 1);
        uint32_t bbase = sb + SB(c & 1);
#pragma unroll
        for (int ks = 0; ks < 4; ks++) {
            uint32_t a0[4], a1[4], a2[4], a3[4];
            uint32_t b0[4], b1[4], b2[4], b3[4];
#pragma unroll
            for (int mt = 0; mt < 4; mt++) {
                int row = warp_m * 64 + mt * 16 + lrow;
                uint32_t addr = abase + row * 128 + (((ks * 2 + lcg) ^ (row & 7)) << 4);
                ldsm_x4(a0[mt], a1[mt], a2[mt], a3[mt], addr);
            }
#pragma unroll
            for (int np = 0; np < 4; np++) {
                int row = warp_n * 64 + np * 16 + lrow;
                uint32_t addr = bbase + row * 128 + (((ks * 2 + lcg) ^ (row & 7)) << 4);
                ldsm_x4(b0[np], b1[np], b2[np], b3[np], addr);
            }
#pragma unroll
            for (int mt = 0; mt < 4; mt++) {
#pragma unroll
                for (int np = 0; np < 4; np++) {
                    mma16816(acc[mt][np * 2][0], acc[mt][np * 2][1],
                             acc[mt][np * 2][2], acc[mt][np * 2][3],
                             a0[mt], a1[mt], a2[mt], a3[mt], b0[np], b2[np]);
                    mma16816(acc[mt][np * 2 + 1][0], acc[mt][np * 2 + 1][1],
                             acc[mt][np * 2 + 1][2], acc[mt][np * 2 + 1][3],
                             a0[mt], a1[mt], a2[mt], a3[mt], b1[np], b3[np]);
                }
            }
        }
        __syncthreads();
    }

    // ---- epilogue: bias + store ----
    const int qm = lane >> 2;
    const int qn = (lane & 3) * 2;
    float2 bb[8];
#pragma unroll
    for (int nt = 0; nt < 8; nt++) {
        int ncol = warp_n * 64 + nt * 8 + qn;
        bb[nt] = *(const float2*)(bias + ncol);
    }
#pragma unroll
    for (int mt = 0; mt < 4; mt++) {
        int r0 = m0 + warp_m * 64 + mt * 16 + qm;
        int r1 = r0 + 8;
#pragma unroll
        for (int nt = 0; nt < 8; nt++) {
            int ncol = warp_n * 64 + nt * 8 + qn;
            if (r0 < GN) {
                float2 v = make_float2(acc[mt][nt][0] + bb[nt].x, acc[mt][nt][1] + bb[nt].y);
                *(float2*)(out + (size_t)r0 * GD + ncol) = v;
            }
            if (r1 < GN) {
                float2 v = make_float2(acc[mt][nt][2] + bb[nt].x, acc[mt][nt][3] + bb[nt].y);
                *(float2*)(out + (size_t)r1 * GD + ncol) = v;
            }
        }
    }
}

// ---------------- launch: two-stream strip pipeline ----------------
extern "C" void kernel_launch(void* const* d_in, const int* in_sizes, int n_in,
                              void* d_out, int out_size) {
    const float* x  = (const float*)d_in[0];
    const int*   ei = (const int*)d_in[1];
    const float* W  = (const float*)d_in[2];
    const float* b  = (const float*)d_in[3];
    float* out = (float*)d_out;
    (void)in_sizes; (void)n_in; (void)out_size;

    static int init_done = 0;
    static int overlap_ok = 1;
    static cudaStream_t s1;
    static cudaEvent_t e0, ev[NSTRIP];
    if (!init_done) {
        init_done = 1;
        cudaFuncSetAttribute(gemm_kernel, cudaFuncAttributeMaxDynamicSharedMemorySize, SMEM_DYN);
        if (cudaStreamCreateWithFlags(&s1, cudaStreamNonBlocking) != cudaSuccess) overlap_ok = 0;
        if (cudaEventCreateWithFlags(&e0, cudaEventDisableTiming) != cudaSuccess) overlap_ok = 0;
        for (int k = 0; k < NSTRIP; k++)
            if (cudaEventCreateWithFlags(&ev[k], cudaEventDisableTiming) != cudaSuccess)
                overlap_ok = 0;
    }

    // phase 0 (main stream): conversions + dtype detect
    int cvt_threads = ((GN + 1) * GD) / 8;
    cvt_x_kernel<<<(cvt_threads + 255) / 256, 256>>>(x);
    cvt_w_kernel<<<(GD * GK / 8 + 255) / 256, 256>>>(W);
    detect_kernel<<<1, 256>>>(ei);

    if (overlap_ok) {
        cudaEventRecord(e0, 0);
        cudaStreamWaitEvent(s1, e0, 0);
        // agg strips on s1 (forked), each records its completion event
        int cta_base = 0;
        for (int k = 0; k < NSTRIP; k++) {
            int nc = TOTAL_CTAS - cta_base; if (nc > STRIP_CTAS) nc = STRIP_CTAS;
            int nbase = cta_base * TILE_M;
            int nend = nbase + nc * TILE_M; if (nend > GN) nend = GN;
            int nodes = nend - nbase;
            agg_kernel<<<(nodes + 7) / 8, 256, 0, s1>>>(ei, nbase, nend);
            cudaEventRecord(ev[k], s1);
            cta_base += nc;
        }
        // gemm strips on main, each gated on its agg strip (joins s1 back)
        cta_base = 0;
        for (int k = 0; k < NSTRIP; k++) {
            int nc = TOTAL_CTAS - cta_base; if (nc > STRIP_CTAS) nc = STRIP_CTAS;
            cudaStreamWaitEvent(0, ev[k], 0);
            gemm_kernel<<<nc, 256, SMEM_DYN>>>(b, out, cta_base * TILE_M);
            cta_base += nc;
        }
    } else {
        // sequential fallback (identical math)
        agg_kernel<<<(GN + 7) / 8, 256>>>(ei, 0, GN);
        gemm_kernel<<<TOTAL_CTAS, 256, SMEM_DYN>>>(b, out, 0);
    }
}

// round 7
// speedup vs baseline: 1.0262x; 1.0133x over previous
#include <cuda_runtime.h>
#include <cuda_fp16.h>
#include <cuda_bf16.h>
#include <cstdint>

// ---------------- problem constants ----------------
#define GN 100000          // nodes
#define GD 256             // d_in = d_out
#define GK 512             // 2*d_in
#define MAXDEG 16

#define TILE_M 64
#define NCTAS ((GN + TILE_M - 1) / TILE_M)   // 1563

// ---------------- scratch (device globals; no allocs allowed) ----------------
__device__ __align__(256) __half g_xh[(GN + 1) * GD];   // x in fp16, + zero row at index GN
__device__ __align__(256) __half g_wh[GK * GD];         // W in fp16, [n][k] row-major
__device__ int g_is64;                                  // edge_index dtype flag

// ---------------- small helpers ----------------
__device__ __forceinline__ uint32_t smem_u32(const void* p) {
    uint32_t a;
    asm("{ .reg .u64 t; cvta.to.shared.u64 t, %1; cvt.u32.u64 %0, t; }" : "=r"(a) : "l"(p));
    return a;
}

__device__ __forceinline__ void cp_async16(uint32_t dst, const void* src, int pred) {
    int sz = pred ? 16 : 0;
    asm volatile("cp.async.cg.shared.global [%0], [%1], 16, %2;"
                 :: "r"(dst), "l"(src), "r"(sz) : "memory");
}
__device__ __forceinline__ void cp_async_commit() {
    asm volatile("cp.async.commit_group;" ::: "memory");
}
__device__ __forceinline__ void cp_async_wait0() {
    asm volatile("cp.async.wait_group 0;" ::: "memory");
}

__device__ __forceinline__ void ldsm_x4(uint32_t& r0, uint32_t& r1, uint32_t& r2, uint32_t& r3,
                                        uint32_t addr) {
    asm volatile("ldmatrix.sync.aligned.m8n8.x4.shared.b16 {%0,%1,%2,%3}, [%4];"
                 : "=r"(r0), "=r"(r1), "=r"(r2), "=r"(r3) : "r"(addr));
}

__device__ __forceinline__ void mma16816(float& c0, float& c1, float& c2, float& c3,
                                         uint32_t a0, uint32_t a1, uint32_t a2, uint32_t a3,
                                         uint32_t b0, uint32_t b1) {
    asm volatile(
        "mma.sync.aligned.m16n8k16.row.col.f32.f16.f16.f32 "
        "{%0,%1,%2,%3}, {%4,%5,%6,%7}, {%8,%9}, {%0,%1,%2,%3};"
        : "+f"(c0), "+f"(c1), "+f"(c2), "+f"(c3)
        : "r"(a0), "r"(a1), "r"(a2), "r"(a3), "r"(b0), "r"(b1));
}

#define STS128U4(addr, v) \
    asm volatile("st.shared.v4.b32 [%0], {%1,%2,%3,%4};" \
        :: "r"(addr), "r"((v).x), "r"((v).y), "r"((v).z), "r"((v).w) : "memory")

// ---------------- kernel 1: x -> fp16 (+ zero pad row) ----------------
__global__ void cvt_x_kernel(const float* __restrict__ x) {
    size_t i = ((size_t)blockIdx.x * blockDim.x + threadIdx.x) * 8;
    const size_t total = (size_t)(GN + 1) * GD;
    if (i >= total) return;
    uint4 o;
    if (i < (size_t)GN * GD) {
        float4 a = *(const float4*)(x + i);
        float4 b = *(const float4*)(x + i + 4);
        __half2 h0 = __floats2half2_rn(a.x, a.y);
        __half2 h1 = __floats2half2_rn(a.z, a.w);
        __half2 h2 = __floats2half2_rn(b.x, b.y);
        __half2 h3 = __floats2half2_rn(b.z, b.w);
        o.x = *reinterpret_cast<unsigned*>(&h0);
        o.y = *reinterpret_cast<unsigned*>(&h1);
        o.z = *reinterpret_cast<unsigned*>(&h2);
        o.w = *reinterpret_cast<unsigned*>(&h3);
    } else {
        o = make_uint4(0, 0, 0, 0);
    }
    *(uint4*)(g_xh + i) = o;
}

// ---------------- kernel 1w: W -> fp16 ----------------
__global__ void cvt_w_kernel(const float* __restrict__ W) {
    size_t i = ((size_t)blockIdx.x * blockDim.x + threadIdx.x) * 8;
    if (i >= (size_t)GD * GK) return;
    float4 a = *(const float4*)(W + i);
    float4 b = *(const float4*)(W + i + 4);
    __half2 h0 = __floats2half2_rn(a.x, a.y);
    __half2 h1 = __floats2half2_rn(a.z, a.w);
    __half2 h2 = __floats2half2_rn(b.x, b.y);
    __half2 h3 = __floats2half2_rn(b.z, b.w);
    uint4 o;
    o.x = *reinterpret_cast<unsigned*>(&h0);
    o.y = *reinterpret_cast<unsigned*>(&h1);
    o.z = *reinterpret_cast<unsigned*>(&h2);
    o.w = *reinterpret_cast<unsigned*>(&h3);
    *(uint4*)(g_wh + i) = o;
}

// ---------------- kernel 1b: detect edge dtype (int32 vs int64) ----------------
__global__ void detect_kernel(const int* __restrict__ e) {
    int v = e[2 * threadIdx.x + 1];           // odd 32-bit words of first rows
    int bad = (v != 0 && v != -1) ? 1 : 0;    // int64 => these are all 0 / -1
    int any = __syncthreads_or(bad);
    if (threadIdx.x == 0) g_is64 = any ? 0 : 1;
}

// ---------------- fused kernel: gather-mean + mma.sync GEMM + bias --------------------
// out[M,256] = [x | mean_nbr(x)] @ W^T + b, per-CTA tile 64(M) x 256(N).
// CTA: 256 thr (8 warps), 2 CTAs/SM. Prologue gathers the agg half of A (chunks 4-7)
// directly into swizzled smem; chunks 0-3 (x half) + all B chunks via cp.async dbuf.
// Warp grid: 8 warps along N (32 cols each), full 64 M rows per warp.

#define KC 64
#define NCH 8

// SMEM layout (bytes): AGG 4 x 8192 @ 0 ; AX dbuf 2 x 8192 @ 32768 ; B dbuf 2 x 32768 @ 49152
#define SM_AGG 0
#define SM_AX(buf) (32768 + (buf) * 8192)
#define SM_B(buf) (49152 + (buf) * 32768)
#define SMEM_DYN 114688

__global__ void __launch_bounds__(256, 2)
fused_kernel(const int* __restrict__ edges, const float* __restrict__ bias,
             float* __restrict__ out) {
    extern __shared__ char smem_raw[];
    uint32_t sb = smem_u32(smem_raw);
    const int tid = threadIdx.x;
    const int wid = tid >> 5, lane = tid & 31;
    const int m0 = blockIdx.x * TILE_M;

    // ---- issue chunk helpers: A = 512 segs (2/thr), B = 2048 segs (8/thr) ----
    auto issue_ax = [&](int c, int buf) {
#pragma unroll
        for (int i = 0; i < 2; i++) {
            int s = tid + i * 256;
            int row = s >> 3, seg = s & 7;
            int m = m0 + row;
            uint32_t dst = sb + SM_AX(buf) + row * 128 + ((seg ^ (row & 7)) << 4);
            cp_async16(dst, g_xh + (size_t)m * GD + c * KC + seg * 8, m < GN);
        }
    };
    auto issue_b = [&](int c, int buf) {
#pragma unroll
        for (int i = 0; i < 8; i++) {
            int s = tid + i * 256;
            int n = s >> 3, seg = s & 7;
            uint32_t dst = sb + SM_B(buf) + n * 128 + ((seg ^ (n & 7)) << 4);
            cp_async16(dst, g_wh + (size_t)n * GK + c * KC + seg * 8, 1);
        }
    };

    // ---- prologue: chunk 0 loads in flight, then gather agg half ----
    issue_ax(0, 0);
    issue_b(0, 0);
    cp_async_commit();

    {
        int is64 = g_is64;
#pragma unroll 1
        for (int rr = 0; rr < 8; rr++) {
            int row = wid * 8 + rr;           // 0..63 within tile
            int m = m0 + row;
            if (m >= GN) continue;            // warp-uniform branch
            int e = -1;
            if (lane < MAXDEG) {
                if (is64) {
                    long long t = ((const long long*)edges)[(size_t)m * MAXDEG + lane];
                    e = (int)t;
                } else {
                    e = edges[m * MAXDEG + lane];
                }
            }
            unsigned bal = __ballot_sync(0xffffffffu, e >= 0);
            float inv = 1.0f / (float)__popc(bal & 0xffffu);

            float acc8[8];
#pragma unroll
            for (int q = 0; q < 8; q++) acc8[q] = 0.0f;

#pragma unroll
            for (int q4 = 0; q4 < 4; q4++) {
                uint4 v[4];
#pragma unroll
                for (int d = 0; d < 4; d++) {
                    int ej = __shfl_sync(0xffffffffu, e, q4 * 4 + d);
                    unsigned rowg = (ej >= 0) ? (unsigned)ej : (unsigned)GN; // pad -> zero row
                    v[d] = *(const uint4*)(g_xh + (size_t)rowg * GD + lane * 8);
                }
                const __half2* p0 = (const __half2*)&v[0];
                const __half2* p1 = (const __half2*)&v[1];
                const __half2* p2 = (const __half2*)&v[2];
                const __half2* p3 = (const __half2*)&v[3];
#pragma unroll
                for (int j = 0; j < 4; j++) {
                    __half2 s01 = __hadd2(p0[j], p1[j]);
                    __half2 s23 = __hadd2(p2[j], p3[j]);
                    __half2 s = __hadd2(s01, s23);
                    float2 f = __half22float2(s);
                    acc8[j * 2] += f.x;
                    acc8[j * 2 + 1] += f.y;
                }
            }
            __half2 r0 = __floats2half2_rn(acc8[0] * inv, acc8[1] * inv);
            __half2 r1 = __floats2half2_rn(acc8[2] * inv, acc8[3] * inv);
            __half2 r2 = __floats2half2_rn(acc8[4] * inv, acc8[5] * inv);
            __half2 r3 = __floats2half2_rn(acc8[6] * inv, acc8[7] * inv);
            uint4 o;
            o.x = *reinterpret_cast<unsigned*>(&r0);
            o.y = *reinterpret_cast<unsigned*>(&r1);
            o.z = *reinterpret_cast<unsigned*>(&r2);
            o.w = *reinterpret_cast<unsigned*>(&r3);
            // lane holds cols [lane*8, lane*8+8) -> chunk (lane>>3), seg (lane&7)
            int chunk = lane >> 3;
            int seg = lane & 7;
            uint32_t dst = sb + SM_AGG + chunk * 8192 + row * 128 + ((seg ^ (row & 7)) << 4);
            STS128U4(dst, o);
        }
    }

    // ---- mainloop ----
    float acc[4][4][4];
#pragma unroll
    for (int mt = 0; mt < 4; mt++)
#pragma unroll
        for (int nt = 0; nt < 4; nt++)
#pragma unroll
            for (int q = 0; q < 4; q++) acc[mt][nt][q] = 0.0f;

    const int lrow = lane & 15;          // row within 16-row tile
    const int lcg = lane >> 4;           // 16B column group (0/1)

#pragma unroll 1
    for (int c = 0; c < NCH; c++) {
        cp_async_wait0();
        __syncthreads();                 // chunk c resident; (c==0 sync also covers agg writes)
        if (c + 1 < NCH) {
            if (c + 1 < 4) issue_ax(c + 1, (c + 1) & 1);
            issue_b(c + 1, (c + 1) & 1);
            cp_async_commit();
        }

        uint32_t abase = (c < 4) ? (sb + SM_AX(c & 1)) : (sb + SM_AGG + (c - 4) * 8192);
        uint32_t bbase = sb + SM_B(c & 1);
#pragma unroll
        for (int ks = 0; ks < 4; ks++) {
            uint32_t a0[4], a1[4], a2[4], a3[4];
            uint32_t b0[2], b1[2], b2[2], b3[2];
#pragma unroll
            for (int mt = 0; mt < 4; mt++) {
                int row = mt * 16 + lrow;
                uint32_t addr = abase + row * 128 + (((ks * 2 + lcg) ^ (row & 7)) << 4);
                ldsm_x4(a0[mt], a1[mt], a2[mt], a3[mt], addr);
            }
#pragma unroll
            for (int np = 0; np < 2; np++) {     // 2 n-tile pairs (16 n-rows each)
                int row = wid * 32 + np * 16 + lrow;
                uint32_t addr = bbase + row * 128 + (((ks * 2 + lcg) ^ (row & 7)) << 4);
                ldsm_x4(b0[np], b1[np], b2[np], b3[np], addr);
            }
#pragma unroll
            for (int mt = 0; mt < 4; mt++) {
#pragma unroll
                for (int np = 0; np < 2; np++) {
                    mma16816(acc[mt][np * 2][0], acc[mt][np * 2][1],
                             acc[mt][np * 2][2], acc[mt][np * 2][3],
                             a0[mt], a1[mt], a2[mt], a3[mt], b0[np], b2[np]);
                    mma16816(acc[mt][np * 2 + 1][0], acc[mt][np * 2 + 1][1],
                             acc[mt][np * 2 + 1][2], acc[mt][np * 2 + 1][3],
                             a0[mt], a1[mt], a2[mt], a3[mt], b1[np], b3[np]);
                }
            }
        }
        __syncthreads();
    }

    // ---- epilogue: bias + store (warp covers rows 0..63, cols wid*32..wid*32+31) ----
    const int qm = lane >> 2;            // 0..7 row within 8
    const int qn = (lane & 3) * 2;       // col pair
    float2 bb[4];
#pragma unroll
    for (int nt = 0; nt < 4; nt++) {
        int ncol = wid * 32 + nt * 8 + qn;
        bb[nt] = *(const float2*)(bias + ncol);
    }
#pragma unroll
    for (int mt = 0; mt < 4; mt++) {
        int r0 = m0 + mt * 16 + qm;
        int r1 = r0 + 8;
#pragma unroll
        for (int nt = 0; nt < 4; nt++) {
            int ncol = wid * 32 + nt * 8 + qn;
            if (r0 < GN) {
                float2 v = make_float2(acc[mt][nt][0] + bb[nt].x, acc[mt][nt][1] + bb[nt].y);
                *(float2*)(out + (size_t)r0 * GD + ncol) = v;
            }
            if (r1 < GN) {
                float2 v = make_float2(acc[mt][nt][2] + bb[nt].x, acc[mt][nt][3] + bb[nt].y);
                *(float2*)(out + (size_t)r1 * GD + ncol) = v;
            }
        }
    }
}

// ---------------- launch ----------------
extern "C" void kernel_launch(void* const* d_in, const int* in_sizes, int n_in,
                              void* d_out, int out_size) {
    const float* x  = (const float*)d_in[0];
    const int*   ei = (const int*)d_in[1];
    const float* W  = (const float*)d_in[2];
    const float* b  = (const float*)d_in[3];
    float* out = (float*)d_out;
    (void)in_sizes; (void)n_in; (void)out_size;

    static int init_done = 0;
    if (!init_done) {
        init_done = 1;
        cudaFuncSetAttribute(fused_kernel, cudaFuncAttributeMaxDynamicSharedMemorySize, SMEM_DYN);
    }

    // 1) x -> fp16 (+ zero pad row), W -> fp16, dtype detect
    int cvt_threads = ((GN + 1) * GD) / 8;
    cvt_x_kernel<<<(cvt_threads + 255) / 256, 256>>>(x);
    cvt_w_kernel<<<(GD * GK / 8 + 255) / 256, 256>>>(W);
    detect_kernel<<<1, 256>>>(ei);
    // 2) fused gather-mean + GEMM + bias
    fused_kernel<<<NCTAS, 256, SMEM_DYN>>>(ei, b, out);
}

// round 8
// speedup vs baseline: 1.0505x; 1.0237x over previous
#include <cuda_runtime.h>
#include <cuda_fp16.h>
#include <cuda_bf16.h>
#include <cstdint>

// ---------------- problem constants ----------------
#define GN 100000          // nodes
#define GD 256             // d_in = d_out
#define GK 512             // 2*d_in
#define MAXDEG 16

#define TILE_M 64
#define NCTAS ((GN + TILE_M - 1) / TILE_M)   // 1563

// ---------------- scratch (device globals; no allocs allowed) ----------------
__device__ __align__(256) __half g_xh[(GN + 1) * GD];   // x in fp16, + zero row at index GN
__device__ __align__(256) __half g_wh[GK * GD];         // W in fp16, [n][k] row-major
__device__ int g_is64;                                  // edge_index dtype flag

// ---------------- small helpers ----------------
__device__ __forceinline__ uint32_t smem_u32(const void* p) {
    uint32_t a;
    asm("{ .reg .u64 t; cvta.to.shared.u64 t, %1; cvt.u32.u64 %0, t; }" : "=r"(a) : "l"(p));
    return a;
}

__device__ __forceinline__ void cp_async16(uint32_t dst, const void* src, int pred) {
    int sz = pred ? 16 : 0;
    asm volatile("cp.async.cg.shared.global [%0], [%1], 16, %2;"
                 :: "r"(dst), "l"(src), "r"(sz) : "memory");
}
__device__ __forceinline__ void cp_async_commit() {
    asm volatile("cp.async.commit_group;" ::: "memory");
}
__device__ __forceinline__ void cp_async_wait0() {
    asm volatile("cp.async.wait_group 0;" ::: "memory");
}

__device__ __forceinline__ void ldsm_x4(uint32_t& r0, uint32_t& r1, uint32_t& r2, uint32_t& r3,
                                        uint32_t addr) {
    asm volatile("ldmatrix.sync.aligned.m8n8.x4.shared.b16 {%0,%1,%2,%3}, [%4];"
                 : "=r"(r0), "=r"(r1), "=r"(r2), "=r"(r3) : "r"(addr));
}

__device__ __forceinline__ void mma16816(float& c0, float& c1, float& c2, float& c3,
                                         uint32_t a0, uint32_t a1, uint32_t a2, uint32_t a3,
                                         uint32_t b0, uint32_t b1) {
    asm volatile(
        "mma.sync.aligned.m16n8k16.row.col.f32.f16.f16.f32 "
        "{%0,%1,%2,%3}, {%4,%5,%6,%7}, {%8,%9}, {%0,%1,%2,%3};"
        : "+f"(c0), "+f"(c1), "+f"(c2), "+f"(c3)
        : "r"(a0), "r"(a1), "r"(a2), "r"(a3), "r"(b0), "r"(b1));
}

#define STS128U4(addr, v) \
    asm volatile("st.shared.v4.b32 [%0], {%1,%2,%3,%4};" \
        :: "r"(addr), "r"((v).x), "r"((v).y), "r"((v).z), "r"((v).w) : "memory")

// ---------------- kernel 1: x -> fp16 (+ zero pad row) ----------------
__global__ void cvt_x_kernel(const float* __restrict__ x) {
    size_t i = ((size_t)blockIdx.x * blockDim.x + threadIdx.x) * 8;
    const size_t total = (size_t)(GN + 1) * GD;
    if (i >= total) return;
    uint4 o;
    if (i < (size_t)GN * GD) {
        float4 a = *(const float4*)(x + i);
        float4 b = *(const float4*)(x + i + 4);
        __half2 h0 = __floats2half2_rn(a.x, a.y);
        __half2 h1 = __floats2half2_rn(a.z, a.w);
        __half2 h2 = __floats2half2_rn(b.x, b.y);
        __half2 h3 = __floats2half2_rn(b.z, b.w);
        o.x = *reinterpret_cast<unsigned*>(&h0);
        o.y = *reinterpret_cast<unsigned*>(&h1);
        o.z = *reinterpret_cast<unsigned*>(&h2);
        o.w = *reinterpret_cast<unsigned*>(&h3);
    } else {
        o = make_uint4(0, 0, 0, 0);
    }
    *(uint4*)(g_xh + i) = o;
}

// ---------------- kernel 1w: W -> fp16 ----------------
__global__ void cvt_w_kernel(const float* __restrict__ W) {
    size_t i = ((size_t)blockIdx.x * blockDim.x + threadIdx.x) * 8;
    if (i >= (size_t)GD * GK) return;
    float4 a = *(const float4*)(W + i);
    float4 b = *(const float4*)(W + i + 4);
    __half2 h0 = __floats2half2_rn(a.x, a.y);
    __half2 h1 = __floats2half2_rn(a.z, a.w);
    __half2 h2 = __floats2half2_rn(b.x, b.y);
    __half2 h3 = __floats2half2_rn(b.z, b.w);
    uint4 o;
    o.x = *reinterpret_cast<unsigned*>(&h0);
    o.y = *reinterpret_cast<unsigned*>(&h1);
    o.z = *reinterpret_cast<unsigned*>(&h2);
    o.w = *reinterpret_cast<unsigned*>(&h3);
    *(uint4*)(g_wh + i) = o;
}

// ---------------- kernel 1b: detect edge dtype (int32 vs int64) ----------------
__global__ void detect_kernel(const int* __restrict__ e) {
    int v = e[2 * threadIdx.x + 1];           // odd 32-bit words of first rows
    int bad = (v != 0 && v != -1) ? 1 : 0;    // int64 => these are all 0 / -1
    int any = __syncthreads_or(bad);
    if (threadIdx.x == 0) g_is64 = any ? 0 : 1;
}

// ---------------- fused kernel: gather-mean + mma.sync GEMM + bias --------------------
// out[M,256] = [x | mean_nbr(x)] @ W^T + b, per-CTA tile 64(M) x 256(N).
// CTA: 256 thr (8 warps), 2 CTAs/SM. Prologue gathers the agg half of A with MLP=16
// (all 16 neighbor rows of a node in flight at once) into swizzled smem; chunks 0-3
// (x half) + all B chunks via cp.async dbuf. Warps: 8 along N (32 cols each).

#define KC 64
#define NCH 8

// SMEM layout (bytes): AGG 4 x 8192 @ 0 ; AX dbuf 2 x 8192 @ 32768 ; B dbuf 2 x 32768 @ 49152
#define SM_AGG 0
#define SM_AX(buf) (32768 + (buf) * 8192)
#define SM_B(buf) (49152 + (buf) * 32768)
#define SMEM_DYN 114688

__global__ void __launch_bounds__(256, 2)
fused_kernel(const int* __restrict__ edges, const float* __restrict__ bias,
             float* __restrict__ out) {
    extern __shared__ char smem_raw[];
    uint32_t sb = smem_u32(smem_raw);
    const int tid = threadIdx.x;
    const int wid = tid >> 5, lane = tid & 31;
    const int m0 = blockIdx.x * TILE_M;

    // ---- issue chunk helpers: A = 512 segs (2/thr), B = 2048 segs (8/thr) ----
    auto issue_ax = [&](int c, int buf) {
#pragma unroll
        for (int i = 0; i < 2; i++) {
            int s = tid + i * 256;
            int row = s >> 3, seg = s & 7;
            int m = m0 + row;
            uint32_t dst = sb + SM_AX(buf) + row * 128 + ((seg ^ (row & 7)) << 4);
            cp_async16(dst, g_xh + (size_t)m * GD + c * KC + seg * 8, m < GN);
        }
    };
    auto issue_b = [&](int c, int buf) {
#pragma unroll
        for (int i = 0; i < 8; i++) {
            int s = tid + i * 256;
            int n = s >> 3, seg = s & 7;
            uint32_t dst = sb + SM_B(buf) + n * 128 + ((seg ^ (n & 7)) << 4);
            cp_async16(dst, g_wh + (size_t)n * GK + c * KC + seg * 8, 1);
        }
    };

    // ---- prologue: chunk 0 loads in flight, then high-MLP gather of agg half ----
    issue_ax(0, 0);
    issue_b(0, 0);
    cp_async_commit();

    {
        const int is64 = g_is64;
        // Prefetch all 8 rows' edge slots for this warp upfront (MLP=8).
        int e8[8];
#pragma unroll
        for (int rr = 0; rr < 8; rr++) {
            int m = m0 + wid * 8 + rr;
            int e = -1;
            if (lane < MAXDEG && m < GN) {
                if (is64) {
                    long long t = ((const long long*)edges)[(size_t)m * MAXDEG + lane];
                    e = (int)t;
                } else {
                    e = edges[m * MAXDEG + lane];
                }
            }
            e8[rr] = e;
        }

#pragma unroll 1
        for (int rr = 0; rr < 8; rr++) {
            int row = wid * 8 + rr;           // 0..63 within tile
            int m = m0 + row;
            if (m >= GN) continue;            // warp-uniform branch
            int e = e8[rr];
            unsigned bal = __ballot_sync(0xffffffffu, e >= 0);
            float inv = 1.0f / (float)__popc(bal & 0xffffu);

            // all 16 neighbor rows in flight at once (MLP=16)
            uint4 v[16];
#pragma unroll
            for (int d = 0; d < 16; d++) {
                int ej = __shfl_sync(0xffffffffu, e, d);
                unsigned rowg = (ej >= 0) ? (unsigned)ej : (unsigned)GN;   // pad -> zero row
                v[d] = *(const uint4*)(g_xh + (size_t)rowg * GD + lane * 8);
            }

            uint4 o;
            unsigned* op = (unsigned*)&o;
#pragma unroll
            for (int j = 0; j < 4; j++) {
                // depth-3 fp16 tree per 8 neighbors, fp32 combine across the two halves
                const __half2* q0 = (const __half2*)&v[0];
                __half2 sA, sB;
                {
                    __half2 s01 = __hadd2(((const __half2*)&v[0])[j], ((const __half2*)&v[1])[j]);
                    __half2 s23 = __hadd2(((const __half2*)&v[2])[j], ((const __half2*)&v[3])[j]);
                    __half2 s45 = __hadd2(((const __half2*)&v[4])[j], ((const __half2*)&v[5])[j]);
                    __half2 s67 = __hadd2(((const __half2*)&v[6])[j], ((const __half2*)&v[7])[j]);
                    sA = __hadd2(__hadd2(s01, s23), __hadd2(s45, s67));
                }
                {
                    __half2 s01 = __hadd2(((const __half2*)&v[8])[j], ((const __half2*)&v[9])[j]);
                    __half2 s23 = __hadd2(((const __half2*)&v[10])[j], ((const __half2*)&v[11])[j]);
                    __half2 s45 = __hadd2(((const __half2*)&v[12])[j], ((const __half2*)&v[13])[j]);
                    __half2 s67 = __hadd2(((const __half2*)&v[14])[j], ((const __half2*)&v[15])[j]);
                    sB = __hadd2(__hadd2(s01, s23), __hadd2(s45, s67));
                }
                float2 fA = __half22float2(sA);
                float2 fB = __half22float2(sB);
                __half2 r = __floats2half2_rn((fA.x + fB.x) * inv, (fA.y + fB.y) * inv);
                op[j] = *reinterpret_cast<unsigned*>(&r);
                (void)q0;
            }
            // lane holds cols [lane*8, lane*8+8) -> chunk (lane>>3), seg (lane&7)
            int chunk = lane >> 3;
            int seg = lane & 7;
            uint32_t dst = sb + SM_AGG + chunk * 8192 + row * 128 + ((seg ^ (row & 7)) << 4);
            STS128U4(dst, o);
        }
    }

    // ---- mainloop ----
    float acc[4][4][4];
#pragma unroll
    for (int mt = 0; mt < 4; mt++)
#pragma unroll
        for (int nt = 0; nt < 4; nt++)
#pragma unroll
            for (int q = 0; q < 4; q++) acc[mt][nt][q] = 0.0f;

    const int lrow = lane & 15;          // row within 16-row tile
    const int lcg = lane >> 4;           // 16B column group (0/1)

#pragma unroll 1
    for (int c = 0; c < NCH; c++) {
        cp_async_wait0();
        __syncthreads();                 // chunk c resident; (c==0 sync also covers agg writes)
        if (c + 1 < NCH) {
            if (c + 1 < 4) issue_ax(c + 1, (c + 1) & 1);
            issue_b(c + 1, (c + 1) & 1);
            cp_async_commit();
        }

        uint32_t abase = (c < 4) ? (sb + SM_AX(c & 1)) : (sb + SM_AGG + (c - 4) * 8192);
        uint32_t bbase = sb + SM_B(c & 1);
#pragma unroll
        for (int ks = 0; ks < 4; ks++) {
            uint32_t a0[4], a1[4], a2[4], a3[4];
            uint32_t b0[2], b1[2], b2[2], b3[2];
#pragma unroll
            for (int mt = 0; mt < 4; mt++) {
                int row = mt * 16 + lrow;
                uint32_t addr = abase + row * 128 + (((ks * 2 + lcg) ^ (row & 7)) << 4);
                ldsm_x4(a0[mt], a1[mt], a2[mt], a3[mt], addr);
            }
#pragma unroll
            for (int np = 0; np < 2; np++) {     // 2 n-tile pairs (16 n-rows each)
                int row = wid * 32 + np * 16 + lrow;
                uint32_t addr = bbase + row * 128 + (((ks * 2 + lcg) ^ (row & 7)) << 4);
                ldsm_x4(b0[np], b1[np], b2[np], b3[np], addr);
            }
#pragma unroll
            for (int mt = 0; mt < 4; mt++) {
#pragma unroll
                for (int np = 0; np < 2; np++) {
                    mma16816(acc[mt][np * 2][0], acc[mt][np * 2][1],
                             acc[mt][np * 2][2], acc[mt][np * 2][3],
                             a0[mt], a1[mt], a2[mt], a3[mt], b0[np], b2[np]);
                    mma16816(acc[mt][np * 2 + 1][0], acc[mt][np * 2 + 1][1],
                             acc[mt][np * 2 + 1][2], acc[mt][np * 2 + 1][3],
                             a0[mt], a1[mt], a2[mt], a3[mt], b1[np], b3[np]);
                }
            }
        }
        __syncthreads();
    }

    // ---- epilogue: bias + store (warp covers rows 0..63, cols wid*32..wid*32+31) ----
    const int qm = lane >> 2;            // 0..7 row within 8
    const int qn = (lane & 3) * 2;       // col pair
    float2 bb[4];
#pragma unroll
    for (int nt = 0; nt < 4; nt++) {
        int ncol = wid * 32 + nt * 8 + qn;
        bb[nt] = *(const float2*)(bias + ncol);
    }
#pragma unroll
    for (int mt = 0; mt < 4; mt++) {
        int r0 = m0 + mt * 16 + qm;
        int r1 = r0 + 8;
#pragma unroll
        for (int nt = 0; nt < 4; nt++) {
            int ncol = wid * 32 + nt * 8 + qn;
            if (r0 < GN) {
                float2 v = make_float2(acc[mt][nt][0] + bb[nt].x, acc[mt][nt][1] + bb[nt].y);
                *(float2*)(out + (size_t)r0 * GD + ncol) = v;
            }
            if (r1 < GN) {
                float2 v = make_float2(acc[mt][nt][2] + bb[nt].x, acc[mt][nt][3] + bb[nt].y);
                *(float2*)(out + (size_t)r1 * GD + ncol) = v;
            }
        }
    }
}

// ---------------- launch ----------------
extern "C" void kernel_launch(void* const* d_in, const int* in_sizes, int n_in,
                              void* d_out, int out_size) {
    const float* x  = (const float*)d_in[0];
    const int*   ei = (const int*)d_in[1];
    const float* W  = (const float*)d_in[2];
    const float* b  = (const float*)d_in[3];
    float* out = (float*)d_out;
    (void)in_sizes; (void)n_in; (void)out_size;

    static int init_done = 0;
    if (!init_done) {
        init_done = 1;
        cudaFuncSetAttribute(fused_kernel, cudaFuncAttributeMaxDynamicSharedMemorySize, SMEM_DYN);
    }

    // 1) x -> fp16 (+ zero pad row), W -> fp16, dtype detect
    int cvt_threads = ((GN + 1) * GD) / 8;
    cvt_x_kernel<<<(cvt_threads + 255) / 256, 256>>>(x);
    cvt_w_kernel<<<(GD * GK / 8 + 255) / 256, 256>>>(W);
    detect_kernel<<<1, 256>>>(ei);
    // 2) fused gather-mean (MLP=16) + GEMM + bias
    fused_kernel<<<NCTAS, 256, SMEM_DYN>>>(ei, b, out);
}